// round 10
// baseline (speedup 1.0000x reference)
#include <cuda_runtime.h>
#include <cuda_bf16.h>
#include <cstdint>

#define NNODES 50000
#define NEDGES 800000
#define SS 2
#define DIN 128
#define DNOISE 64
#define DH0 192   /* 128 + 64 */
#define DH1 256
#define MROWS (SS*NNODES)                 /* 100000 */
#define OUT_MAIN ((size_t)MROWS*DH1)      /* 25,600,000 */
#define EPS_ELEMS ((size_t)MROWS*DNOISE)

// ---------------- scratch (static device globals; no allocation) ------------
__device__ float g_z0[(size_t)MROWS*DH0];
__device__ float g_h1[(size_t)MROWS*DH1];
__device__ float g_z1[(size_t)MROWS*DH1];
__device__ int   g_deg[NNODES];
__device__ int   g_rowptr[NNODES+1];
__device__ int   g_cursor[NNODES];
__device__ int   g_nbr[NEDGES];
__device__ unsigned g_ebits[(size_t)MROWS*2];   // 64 noise bits -> 2 words per row
// pre-split weights, natural [K][256] layout, bf16 hi/lo
__device__ __nv_bfloat16 g_w0h[DH0*256];
__device__ __nv_bfloat16 g_w0l[DH0*256];
__device__ __nv_bfloat16 g_w1h[DH1*256];
__device__ __nv_bfloat16 g_w1l[DH1*256];

// ---------------- helpers ----------------------------------------------------
__device__ __forceinline__ uint32_t smem_u32(const void* p) {
    uint32_t a;
    asm("{ .reg .u64 t; cvta.to.shared.u64 t, %1; cvt.u32.u64 %0, t; }"
        : "=r"(a) : "l"(p));
    return a;
}
__device__ __forceinline__ void ldsm_x4(uint32_t* r, uint32_t a) {
    asm volatile("ldmatrix.sync.aligned.m8n8.x4.shared.b16 {%0,%1,%2,%3}, [%4];"
                 : "=r"(r[0]), "=r"(r[1]), "=r"(r[2]), "=r"(r[3]) : "r"(a));
}
__device__ __forceinline__ void ldsm_x4_t(uint32_t* r, uint32_t a) {
    asm volatile("ldmatrix.sync.aligned.m8n8.x4.trans.shared.b16 {%0,%1,%2,%3}, [%4];"
                 : "=r"(r[0]), "=r"(r[1]), "=r"(r[2]), "=r"(r[3]) : "r"(a));
}
__device__ __forceinline__ void mma_bf16(float* c, const uint32_t* a, const uint32_t* b) {
    asm volatile("mma.sync.aligned.m16n8k16.row.col.f32.bf16.bf16.f32 "
                 "{%0,%1,%2,%3}, {%4,%5,%6,%7}, {%8,%9}, {%0,%1,%2,%3};"
                 : "+f"(c[0]), "+f"(c[1]), "+f"(c[2]), "+f"(c[3])
                 : "r"(a[0]), "r"(a[1]), "r"(a[2]), "r"(a[3]),
                   "r"(b[0]), "r"(b[1]));
}

// ---------------- fused init: zero degrees + split both weight matrices ------
__global__ void init_kernel(const float* __restrict__ W0, const float* __restrict__ W1) {
    int idx = blockIdx.x * blockDim.x + threadIdx.x;
    if (idx < NNODES) g_deg[idx] = 0;
    if (idx < DH0 * 256) {
        float v = W0[idx];
        __nv_bfloat16 h = __float2bfloat16_rn(v);
        g_w0h[idx] = h;
        g_w0l[idx] = __float2bfloat16_rn(v - __bfloat162float(h));
    }
    if (idx < DH1 * 256) {
        float v = W1[idx];
        __nv_bfloat16 h = __float2bfloat16_rn(v);
        g_w1h[idx] = h;
        g_w1l[idx] = __float2bfloat16_rn(v - __bfloat162float(h));
    }
}

// ---------------- pack epsilon (exact {0,1}) into bitmask words --------------
// word layout: g_ebits[sn*2 + w] covers eps[sn*64 + w*32 .. +31]
__global__ void pack_eps_kernel(const float* __restrict__ eps) {
    int g = blockIdx.x * blockDim.x + threadIdx.x;
    int warp = g >> 5, lane = g & 31;
    if (warp >= MROWS * 2) return;
    float v = eps[(size_t)warp * 32 + lane];
    unsigned m = __ballot_sync(0xffffffffu, v > 0.5f);
    if (lane == 0) g_ebits[warp] = m;
}

// ---------------- CSR build --------------------------------------------------
__global__ void count_deg_kernel(const int* __restrict__ edst) {
    int e = blockIdx.x * blockDim.x + threadIdx.x;
    if (e < NEDGES) atomicAdd(&g_deg[edst[e]], 1);
}
// single-block scan of all 50000 degrees (1024 threads x 49 elements)
__global__ void scan_all_kernel() {
    __shared__ int part[1024];
    const int t = threadIdx.x;
    const int CH = 49;                    // 1024*49 = 50176 >= NNODES
    int base = t * CH;
    int sum = 0;
    #pragma unroll
    for (int k = 0; k < CH; k++) {
        int i = base + k;
        if (i < NNODES) sum += g_deg[i];
    }
    part[t] = sum;
    __syncthreads();
    #pragma unroll
    for (int off = 1; off < 1024; off <<= 1) {
        int x = (t >= off) ? part[t - off] : 0;
        __syncthreads();
        part[t] += x;
        __syncthreads();
    }
    int run = part[t] - sum;              // exclusive prefix of this chunk
    #pragma unroll
    for (int k = 0; k < CH; k++) {
        int i = base + k;
        if (i < NNODES) {
            g_rowptr[i] = run;
            g_cursor[i] = run;
            run += g_deg[i];
        }
    }
    if (t == 0) g_rowptr[NNODES] = NEDGES;
}
__global__ void fill_kernel(const int* __restrict__ esrc, const int* __restrict__ edst) {
    int e = blockIdx.x * blockDim.x + threadIdx.x;
    if (e < NEDGES) {
        int pos = atomicAdd(&g_cursor[edst[e]], 1);
        g_nbr[pos] = esrc[e];
    }
}

// ---------------- fused layer-0 aggregation ----------------------------------
// z0[s,n,:] = (1+eps0)*concat(X[n],eps[s,n]) + sum_nbr concat(X[nbr],eps[s,nbr])
// threads 0..127: X part (shared across samples); 128..191: noise from bitmask.
__global__ void agg0_kernel(const float* __restrict__ X,
                            float* __restrict__ z,
                            const float* __restrict__ eps0p) {
    int n = blockIdx.x;
    int c = threadIdx.x;                 // 0..191
    int beg = g_rowptr[n], end = g_rowptr[n + 1];
    float e1p = 1.0f + *eps0p;
    if (c < DIN) {
        float acc = 0.f;
        int i = beg;
        for (; i + 4 <= end; i += 4) {
            int s0 = g_nbr[i], s1 = g_nbr[i+1], s2 = g_nbr[i+2], s3 = g_nbr[i+3];
            float v0 = X[(size_t)s0 * DIN + c];
            float v1 = X[(size_t)s1 * DIN + c];
            float v2 = X[(size_t)s2 * DIN + c];
            float v3 = X[(size_t)s3 * DIN + c];
            acc += (v0 + v1) + (v2 + v3);
        }
        for (; i < end; i++) acc += X[(size_t)g_nbr[i] * DIN + c];
        float v = fmaf(e1p, X[(size_t)n * DIN + c], acc);
        z[(size_t)n * DH0 + c]            = v;
        z[((size_t)NNODES + n) * DH0 + c] = v;
    } else {
        int cc = c - DIN;                 // 0..63
        int w = cc >> 5, b = cc & 31;
        int cnt0 = 0, cnt1 = 0;
        int i = beg;
        for (; i + 4 <= end; i += 4) {
            int s0 = g_nbr[i], s1 = g_nbr[i+1], s2 = g_nbr[i+2], s3 = g_nbr[i+3];
            unsigned a0 = g_ebits[(size_t)s0 * 2 + w];
            unsigned a1 = g_ebits[(size_t)s1 * 2 + w];
            unsigned a2 = g_ebits[(size_t)s2 * 2 + w];
            unsigned a3 = g_ebits[(size_t)s3 * 2 + w];
            unsigned c0 = g_ebits[((size_t)NNODES + s0) * 2 + w];
            unsigned c1 = g_ebits[((size_t)NNODES + s1) * 2 + w];
            unsigned c2 = g_ebits[((size_t)NNODES + s2) * 2 + w];
            unsigned c3 = g_ebits[((size_t)NNODES + s3) * 2 + w];
            cnt0 += ((a0 >> b) & 1) + ((a1 >> b) & 1) + ((a2 >> b) & 1) + ((a3 >> b) & 1);
            cnt1 += ((c0 >> b) & 1) + ((c1 >> b) & 1) + ((c2 >> b) & 1) + ((c3 >> b) & 1);
        }
        for (; i < end; i++) {
            int s = g_nbr[i];
            cnt0 += (g_ebits[(size_t)s * 2 + w] >> b) & 1;
            cnt1 += (g_ebits[((size_t)NNODES + s) * 2 + w] >> b) & 1;
        }
        float self0 = (float)((g_ebits[(size_t)n * 2 + w] >> b) & 1);
        float self1 = (float)((g_ebits[((size_t)NNODES + n) * 2 + w] >> b) & 1);
        z[(size_t)n * DH0 + c]            = fmaf(e1p, self0, (float)cnt0);
        z[((size_t)NNODES + n) * DH0 + c] = fmaf(e1p, self1, (float)cnt1);
    }
}

// ---------------- layer-1 aggregation ----------------------------------------
template <int D>
__global__ void agg_kernel(const float* __restrict__ h, float* __restrict__ z,
                           const float* __restrict__ eps_ptr) {
    int n = blockIdx.x;
    int c = threadIdx.x;
    int beg = g_rowptr[n], end = g_rowptr[n + 1];
    const float* h1 = h + (size_t)NNODES * D;
    float a0 = 0.f, a1 = 0.f;
    int i = beg;
    for (; i + 2 <= end; i += 2) {
        int s0 = g_nbr[i], s1 = g_nbr[i+1];
        float u0 = h [(size_t)s0 * D + c];
        float u1 = h [(size_t)s1 * D + c];
        float w0 = h1[(size_t)s0 * D + c];
        float w1 = h1[(size_t)s1 * D + c];
        a0 += u0 + u1;
        a1 += w0 + w1;
    }
    for (; i < end; i++) {
        int s = g_nbr[i];
        a0 += h [(size_t)s * D + c];
        a1 += h1[(size_t)s * D + c];
    }
    float e1p = 1.0f + *eps_ptr;
    z[(size_t)n * D + c]            = fmaf(e1p, h [(size_t)n * D + c], a0);
    z[((size_t)NNODES + n) * D + c] = fmaf(e1p, h1[(size_t)n * D + c], a1);
}

// ---------------- bf16x3 mma.sync GEMM: C = relu(A[M,K] @ W[K,256] + b) ------
// BM=128, BN=128, BK=32. 8 warps: 4 (M) x 2 (N); warp tile 32x64.
template <int K>
__global__ void __launch_bounds__(256, 1)
gemm_mma(const float* __restrict__ A, const __nv_bfloat16* __restrict__ Wh,
         const __nv_bfloat16* __restrict__ Wl, const float* __restrict__ bias,
         float* __restrict__ C, int M) {
    constexpr int NST = K / 32;
    constexpr int AH = 0, AL = 5120, BH = 10240, BL = 14592, STG = 18944; // halves

    extern __shared__ __align__(16) __nv_bfloat16 sh[];
    const uint32_t shb = smem_u32(sh);

    const int tid = threadIdx.x;
    const int lane = tid & 31, wid = tid >> 5;
    const int wm = wid & 3;
    const int wn = wid >> 2;
    const int mBase = blockIdx.x * 128;
    const int nCta = blockIdx.y * 128;

    float acc[2][8][4];
    #pragma unroll
    for (int i = 0; i < 2; i++)
        #pragma unroll
        for (int j = 0; j < 8; j++)
            #pragma unroll
            for (int q = 0; q < 4; q++) acc[i][j][q] = 0.f;

    float4 pa[4];
    uint4 pbh[2], pbl[2];

    auto load_g = [&](int s) {
        const int kt = s * 32;
        #pragma unroll
        for (int i = 0; i < 4; i++) {
            int idx = i * 256 + tid;
            int row = idx >> 3, c4 = idx & 7;
            int gr = mBase + row;
            pa[i] = (gr < M) ? *(const float4*)&A[(size_t)gr * K + kt + c4 * 4]
                             : make_float4(0.f, 0.f, 0.f, 0.f);
        }
        #pragma unroll
        for (int i = 0; i < 2; i++) {
            int idx = i * 256 + tid;
            int brow = idx >> 4, c8 = idx & 15;
            size_t g = (size_t)(kt + brow) * 256 + nCta + c8 * 8;
            pbh[i] = *(const uint4*)&Wh[g];
            pbl[i] = *(const uint4*)&Wl[g];
        }
    };

    auto store_s = [&](int buf) {
        __nv_bfloat16* base = sh + buf * STG;
        #pragma unroll
        for (int i = 0; i < 4; i++) {
            int idx = i * 256 + tid;
            int row = idx >> 3, c4 = idx & 7;
            const float* v = (const float*)&pa[i];
            uint32_t hh[2], ll[2];
            #pragma unroll
            for (int p = 0; p < 2; p++) {
                float x0 = v[2 * p], x1 = v[2 * p + 1];
                __nv_bfloat16 h0 = __float2bfloat16_rn(x0);
                __nv_bfloat16 h1 = __float2bfloat16_rn(x1);
                float l0 = x0 - __bfloat162float(h0);
                float l1 = x1 - __bfloat162float(h1);
                __nv_bfloat162 hw; hw.x = h0; hw.y = h1;
                __nv_bfloat162 lw; lw.x = __float2bfloat16_rn(l0);
                lw.y = __float2bfloat16_rn(l1);
                hh[p] = *(uint32_t*)&hw;
                ll[p] = *(uint32_t*)&lw;
            }
            *(uint2*)&base[AH + row * 40 + c4 * 4] = make_uint2(hh[0], hh[1]);
            *(uint2*)&base[AL + row * 40 + c4 * 4] = make_uint2(ll[0], ll[1]);
        }
        #pragma unroll
        for (int i = 0; i < 2; i++) {
            int idx = i * 256 + tid;
            int brow = idx >> 4, c8 = idx & 15;
            *(uint4*)&base[BH + brow * 136 + c8 * 8] = pbh[i];
            *(uint4*)&base[BL + brow * 136 + c8 * 8] = pbl[i];
        }
    };

    auto compute = [&](int buf) {
        const uint32_t base = shb + (uint32_t)buf * STG * 2;   // bytes
        #pragma unroll
        for (int k16 = 0; k16 < 2; k16++) {
            const int krow = k16 * 16;
            uint32_t ah[2][4], al[2][4], bh[8][2], bl[8][2];
            #pragma unroll
            for (int i = 0; i < 2; i++) {
                uint32_t ra = base + (uint32_t)(AH * 2) +
                    (uint32_t)(((wm * 32 + i * 16 + (lane & 15)) * 40 +
                                krow + ((lane >> 4) << 3)) * 2);
                ldsm_x4(ah[i], ra);
                ldsm_x4(al[i], ra + (uint32_t)((AL - AH) * 2));
            }
            #pragma unroll
            for (int j = 0; j < 4; j++) {
                uint32_t rb = base + (uint32_t)(BH * 2) +
                    (uint32_t)(((krow + (lane & 15)) * 136 +
                                wn * 64 + j * 16 + ((lane >> 4) << 3)) * 2);
                uint32_t t[4];
                ldsm_x4_t(t, rb);
                bh[2*j][0] = t[0]; bh[2*j][1] = t[1];
                bh[2*j+1][0] = t[2]; bh[2*j+1][1] = t[3];
                ldsm_x4_t(t, rb + (uint32_t)((BL - BH) * 2));
                bl[2*j][0] = t[0]; bl[2*j][1] = t[1];
                bl[2*j+1][0] = t[2]; bl[2*j+1][1] = t[3];
            }
            #pragma unroll
            for (int i = 0; i < 2; i++)
                #pragma unroll
                for (int j = 0; j < 8; j++) {
                    mma_bf16(acc[i][j], ah[i], bh[j]);
                    mma_bf16(acc[i][j], al[i], bh[j]);
                    mma_bf16(acc[i][j], ah[i], bl[j]);
                }
        }
    };

    load_g(0);
    store_s(0);
    __syncthreads();
    #pragma unroll
    for (int s = 0; s < NST; s++) {
        if (s + 1 < NST) load_g(s + 1);
        compute(s & 1);
        if (s + 1 < NST) {
            store_s((s + 1) & 1);
            __syncthreads();
        }
    }

    // epilogue: bias + relu, float2 stores
    const int trow = lane >> 2;
    const int tcol = (lane & 3) * 2;
    #pragma unroll
    for (int i = 0; i < 2; i++) {
        int r0 = mBase + wm * 32 + i * 16 + trow;
        #pragma unroll
        for (int j = 0; j < 8; j++) {
            int col = nCta + wn * 64 + j * 8 + tcol;
            float2 bv = *(const float2*)&bias[col];
            if (r0 < M) {
                float2 o;
                o.x = fmaxf(acc[i][j][0] + bv.x, 0.f);
                o.y = fmaxf(acc[i][j][1] + bv.y, 0.f);
                *(float2*)&C[(size_t)r0 * 256 + col] = o;
            }
            if (r0 + 8 < M) {
                float2 o;
                o.x = fmaxf(acc[i][j][2] + bv.x, 0.f);
                o.y = fmaxf(acc[i][j][3] + bv.y, 0.f);
                *(float2*)&C[(size_t)(r0 + 8) * 256 + col] = o;
            }
        }
    }
}

// ---------------- launch -----------------------------------------------------
extern "C" void kernel_launch(void* const* d_in, const int* in_sizes, int n_in,
                              void* d_out, int out_size) {
    const float* X    = (const float*)d_in[0];
    const float* eps  = (const float*)d_in[1];
    const int*   esrc = (const int*)d_in[2];
    const int*   edst = (const int*)d_in[3];
    const float* W0   = (const float*)d_in[4];
    const float* b0   = (const float*)d_in[5];
    const float* W1   = (const float*)d_in[6];
    const float* b1   = (const float*)d_in[7];
    const float* e0   = (const float*)d_in[8];
    const float* e1   = (const float*)d_in[9];
    float* out = (float*)d_out;

    float *z0, *h1, *z1;
    __nv_bfloat16 *w0h, *w0l, *w1h, *w1l;
    cudaGetSymbolAddress((void**)&z0, g_z0);
    cudaGetSymbolAddress((void**)&h1, g_h1);
    cudaGetSymbolAddress((void**)&z1, g_z1);
    cudaGetSymbolAddress((void**)&w0h, g_w0h);
    cudaGetSymbolAddress((void**)&w0l, g_w0l);
    cudaGetSymbolAddress((void**)&w1h, g_w1h);
    cudaGetSymbolAddress((void**)&w1l, g_w1l);

    const int DYN = 2 * 18944 * 2;   // 75776 bytes
    cudaFuncSetAttribute(gemm_mma<DH0>, cudaFuncAttributeMaxDynamicSharedMemorySize, DYN);
    cudaFuncSetAttribute(gemm_mma<DH1>, cudaFuncAttributeMaxDynamicSharedMemorySize, DYN);

    // 1) fused init (deg zero + weight split), eps bit-pack, CSR build
    init_kernel<<<(DH1 * 256 + 255) / 256, 256>>>(W0, W1);
    pack_eps_kernel<<<(MROWS * 2 * 32 + 255) / 256, 256>>>(eps);
    count_deg_kernel<<<(NEDGES + 255) / 256, 256>>>(edst);
    scan_all_kernel<<<1, 1024>>>();
    fill_kernel<<<(NEDGES + 255) / 256, 256>>>(esrc, edst);

    dim3 ggrid((MROWS + 127) / 128, 2);

    // 2) layer 0
    agg0_kernel<<<NNODES, DH0>>>(X, z0, e0);
    gemm_mma<DH0><<<ggrid, 256, DYN>>>(z0, w0h, w0l, b0, h1, MROWS);

    // 3) layer 1 (outer relu idempotent with layer relu)
    agg_kernel<DH1><<<NNODES, DH1>>>(h1, z1, e1);
    gemm_mma<DH1><<<ggrid, 256, DYN>>>(z1, w1h, w1l, b1, out, MROWS);

    // 4) second output (epsilon) if the harness buffer includes it
    if ((size_t)out_size >= OUT_MAIN + EPS_ELEMS) {
        cudaMemcpyAsync(out + OUT_MAIN, eps, EPS_ELEMS * sizeof(float),
                        cudaMemcpyDeviceToDevice);
    }
}

// round 13
// speedup vs baseline: 1.1241x; 1.1241x over previous
#include <cuda_runtime.h>
#include <cuda_bf16.h>
#include <cstdint>

#define NNODES 50000
#define NEDGES 800000
#define SS 2
#define DIN 128
#define DNOISE 64
#define DH0 192   /* 128 + 64 */
#define DH1 256
#define MROWS (SS*NNODES)                 /* 100000 */
#define OUT_MAIN ((size_t)MROWS*DH1)      /* 25,600,000 */
#define EPS_ELEMS ((size_t)MROWS*DNOISE)
#define NSCANB ((NNODES + 255) / 256)     /* 196 */

// ---------------- scratch (static device globals; no allocation) ------------
__device__ float g_z0[(size_t)MROWS*DH0];
__device__ float g_h1[(size_t)MROWS*DH1];
__device__ float g_z1[(size_t)MROWS*DH1];
__device__ int   g_deg[NNODES];
__device__ int   g_rowptr[NNODES+1];
__device__ int   g_cursor[NNODES];
__device__ int   g_nbr[NEDGES];
__device__ int   g_bsum[256];
__device__ unsigned g_ebits[(size_t)MROWS*2];   // 64 noise bits -> 2 words per row
// pre-split weights, natural [K][256] layout, bf16 hi/lo
__device__ __nv_bfloat16 g_w0h[DH0*256];
__device__ __nv_bfloat16 g_w0l[DH0*256];
__device__ __nv_bfloat16 g_w1h[DH1*256];
__device__ __nv_bfloat16 g_w1l[DH1*256];

// ---------------- helpers ----------------------------------------------------
__device__ __forceinline__ uint32_t smem_u32(const void* p) {
    uint32_t a;
    asm("{ .reg .u64 t; cvta.to.shared.u64 t, %1; cvt.u32.u64 %0, t; }"
        : "=r"(a) : "l"(p));
    return a;
}
__device__ __forceinline__ void ldsm_x4(uint32_t* r, uint32_t a) {
    asm volatile("ldmatrix.sync.aligned.m8n8.x4.shared.b16 {%0,%1,%2,%3}, [%4];"
                 : "=r"(r[0]), "=r"(r[1]), "=r"(r[2]), "=r"(r[3]) : "r"(a));
}
__device__ __forceinline__ void ldsm_x4_t(uint32_t* r, uint32_t a) {
    asm volatile("ldmatrix.sync.aligned.m8n8.x4.trans.shared.b16 {%0,%1,%2,%3}, [%4];"
                 : "=r"(r[0]), "=r"(r[1]), "=r"(r[2]), "=r"(r[3]) : "r"(a));
}
__device__ __forceinline__ void mma_bf16(float* c, const uint32_t* a, const uint32_t* b) {
    asm volatile("mma.sync.aligned.m16n8k16.row.col.f32.bf16.bf16.f32 "
                 "{%0,%1,%2,%3}, {%4,%5,%6,%7}, {%8,%9}, {%0,%1,%2,%3};"
                 : "+f"(c[0]), "+f"(c[1]), "+f"(c[2]), "+f"(c[3])
                 : "r"(a[0]), "r"(a[1]), "r"(a[2]), "r"(a[3]),
                   "r"(b[0]), "r"(b[1]));
}

// ---------------- fused init: zero degrees + split both weight matrices ------
__global__ void init_kernel(const float* __restrict__ W0, const float* __restrict__ W1) {
    int idx = blockIdx.x * blockDim.x + threadIdx.x;
    if (idx < NNODES) g_deg[idx] = 0;
    if (idx < DH0 * 256) {
        float v = W0[idx];
        __nv_bfloat16 h = __float2bfloat16_rn(v);
        g_w0h[idx] = h;
        g_w0l[idx] = __float2bfloat16_rn(v - __bfloat162float(h));
    }
    if (idx < DH1 * 256) {
        float v = W1[idx];
        __nv_bfloat16 h = __float2bfloat16_rn(v);
        g_w1h[idx] = h;
        g_w1l[idx] = __float2bfloat16_rn(v - __bfloat162float(h));
    }
}

// ---------------- pack epsilon (exact {0,1}) into bitmask words --------------
__global__ void pack_eps_kernel(const float* __restrict__ eps) {
    int g = blockIdx.x * blockDim.x + threadIdx.x;
    int warp = g >> 5, lane = g & 31;
    if (warp >= MROWS * 2) return;
    float v = eps[(size_t)warp * 32 + lane];
    unsigned m = __ballot_sync(0xffffffffu, v > 0.5f);
    if (lane == 0) g_ebits[warp] = m;
}

// ---------------- CSR build (proven multi-block scan) ------------------------
__global__ void count_deg_kernel(const int* __restrict__ edst) {
    int e = blockIdx.x * blockDim.x + threadIdx.x;
    if (e < NEDGES) atomicAdd(&g_deg[edst[e]], 1);
}
__global__ void block_scan_kernel() {
    __shared__ int sdata[256];
    int b = blockIdx.x, t = threadIdx.x;
    int idx = b * 256 + t;
    int v = (idx < NNODES) ? g_deg[idx] : 0;
    sdata[t] = v;
    __syncthreads();
    #pragma unroll
    for (int off = 1; off < 256; off <<= 1) {
        int x = (t >= off) ? sdata[t - off] : 0;
        __syncthreads();
        sdata[t] += x;
        __syncthreads();
    }
    if (idx < NNODES) g_rowptr[idx] = sdata[t] - v;
    if (t == 255) g_bsum[b] = sdata[255];
}
__global__ void scan_bsum_kernel() {
    __shared__ int sdata[256];
    int t = threadIdx.x;
    int v = (t < NSCANB) ? g_bsum[t] : 0;
    sdata[t] = v;
    __syncthreads();
    #pragma unroll
    for (int off = 1; off < 256; off <<= 1) {
        int x = (t >= off) ? sdata[t - off] : 0;
        __syncthreads();
        sdata[t] += x;
        __syncthreads();
    }
    g_bsum[t] = sdata[t] - v;
}
__global__ void add_off_kernel() {
    int idx = blockIdx.x * blockDim.x + threadIdx.x;
    if (idx < NNODES) {
        int r = g_rowptr[idx] + g_bsum[idx >> 8];
        g_rowptr[idx] = r;
        g_cursor[idx] = r;
    }
    if (idx == 0) g_rowptr[NNODES] = NEDGES;
}
__global__ void fill_kernel(const int* __restrict__ esrc, const int* __restrict__ edst) {
    int e = blockIdx.x * blockDim.x + threadIdx.x;
    if (e < NEDGES) {
        int pos = atomicAdd(&g_cursor[edst[e]], 1);
        g_nbr[pos] = esrc[e];
    }
}

// ---------------- fused layer-0 aggregation ----------------------------------
// threads 0..127: X part (shared across samples); 128..191: noise from bitmask.
__global__ void agg0_kernel(const float* __restrict__ X,
                            float* __restrict__ z,
                            const float* __restrict__ eps0p) {
    int n = blockIdx.x;
    int c = threadIdx.x;                 // 0..191
    int beg = g_rowptr[n], end = g_rowptr[n + 1];
    float e1p = 1.0f + *eps0p;
    if (c < DIN) {
        float acc = 0.f;
        int i = beg;
        for (; i + 4 <= end; i += 4) {
            int s0 = g_nbr[i], s1 = g_nbr[i+1], s2 = g_nbr[i+2], s3 = g_nbr[i+3];
            float v0 = X[(size_t)s0 * DIN + c];
            float v1 = X[(size_t)s1 * DIN + c];
            float v2 = X[(size_t)s2 * DIN + c];
            float v3 = X[(size_t)s3 * DIN + c];
            acc += (v0 + v1) + (v2 + v3);
        }
        for (; i < end; i++) acc += X[(size_t)g_nbr[i] * DIN + c];
        float v = fmaf(e1p, X[(size_t)n * DIN + c], acc);
        z[(size_t)n * DH0 + c]            = v;
        z[((size_t)NNODES + n) * DH0 + c] = v;
    } else {
        int cc = c - DIN;                 // 0..63
        int w = cc >> 5, b = cc & 31;
        int cnt0 = 0, cnt1 = 0;
        int i = beg;
        for (; i + 4 <= end; i += 4) {
            int s0 = g_nbr[i], s1 = g_nbr[i+1], s2 = g_nbr[i+2], s3 = g_nbr[i+3];
            unsigned a0 = g_ebits[(size_t)s0 * 2 + w];
            unsigned a1 = g_ebits[(size_t)s1 * 2 + w];
            unsigned a2 = g_ebits[(size_t)s2 * 2 + w];
            unsigned a3 = g_ebits[(size_t)s3 * 2 + w];
            unsigned c0 = g_ebits[((size_t)NNODES + s0) * 2 + w];
            unsigned c1 = g_ebits[((size_t)NNODES + s1) * 2 + w];
            unsigned c2 = g_ebits[((size_t)NNODES + s2) * 2 + w];
            unsigned c3 = g_ebits[((size_t)NNODES + s3) * 2 + w];
            cnt0 += ((a0 >> b) & 1) + ((a1 >> b) & 1) + ((a2 >> b) & 1) + ((a3 >> b) & 1);
            cnt1 += ((c0 >> b) & 1) + ((c1 >> b) & 1) + ((c2 >> b) & 1) + ((c3 >> b) & 1);
        }
        for (; i < end; i++) {
            int s = g_nbr[i];
            cnt0 += (g_ebits[(size_t)s * 2 + w] >> b) & 1;
            cnt1 += (g_ebits[((size_t)NNODES + s) * 2 + w] >> b) & 1;
        }
        float self0 = (float)((g_ebits[(size_t)n * 2 + w] >> b) & 1);
        float self1 = (float)((g_ebits[((size_t)NNODES + n) * 2 + w] >> b) & 1);
        z[(size_t)n * DH0 + c]            = fmaf(e1p, self0, (float)cnt0);
        z[((size_t)NNODES + n) * DH0 + c] = fmaf(e1p, self1, (float)cnt1);
    }
}

// ---------------- layer-1 aggregation ----------------------------------------
template <int D>
__global__ void agg_kernel(const float* __restrict__ h, float* __restrict__ z,
                           const float* __restrict__ eps_ptr) {
    int n = blockIdx.x;
    int c = threadIdx.x;
    int beg = g_rowptr[n], end = g_rowptr[n + 1];
    const float* h1 = h + (size_t)NNODES * D;
    float a0 = 0.f, a1 = 0.f;
    int i = beg;
    for (; i + 2 <= end; i += 2) {
        int s0 = g_nbr[i], s1 = g_nbr[i+1];
        float u0 = h [(size_t)s0 * D + c];
        float u1 = h [(size_t)s1 * D + c];
        float w0 = h1[(size_t)s0 * D + c];
        float w1 = h1[(size_t)s1 * D + c];
        a0 += u0 + u1;
        a1 += w0 + w1;
    }
    for (; i < end; i++) {
        int s = g_nbr[i];
        a0 += h [(size_t)s * D + c];
        a1 += h1[(size_t)s * D + c];
    }
    float e1p = 1.0f + *eps_ptr;
    z[(size_t)n * D + c]            = fmaf(e1p, h [(size_t)n * D + c], a0);
    z[((size_t)NNODES + n) * D + c] = fmaf(e1p, h1[(size_t)n * D + c], a1);
}

// ---------------- bf16x3 mma.sync GEMM: C = relu(A[M,K] @ W[K,256] + b) ------
// BM=128, BN=128, BK=32. 8 warps: 4 (M) x 2 (N); warp tile 32x64.
template <int K>
__global__ void __launch_bounds__(256, 1)
gemm_mma(const float* __restrict__ A, const __nv_bfloat16* __restrict__ Wh,
         const __nv_bfloat16* __restrict__ Wl, const float* __restrict__ bias,
         float* __restrict__ C, int M) {
    constexpr int NST = K / 32;
    constexpr int AH = 0, AL = 5120, BH = 10240, BL = 14592, STG = 18944; // halves

    extern __shared__ __align__(16) __nv_bfloat16 sh[];
    const uint32_t shb = smem_u32(sh);

    const int tid = threadIdx.x;
    const int lane = tid & 31, wid = tid >> 5;
    const int wm = wid & 3;
    const int wn = wid >> 2;
    const int mBase = blockIdx.x * 128;
    const int nCta = blockIdx.y * 128;

    float acc[2][8][4];
    #pragma unroll
    for (int i = 0; i < 2; i++)
        #pragma unroll
        for (int j = 0; j < 8; j++)
            #pragma unroll
            for (int q = 0; q < 4; q++) acc[i][j][q] = 0.f;

    float4 pa[4];
    uint4 pbh[2], pbl[2];

    auto load_g = [&](int s) {
        const int kt = s * 32;
        #pragma unroll
        for (int i = 0; i < 4; i++) {
            int idx = i * 256 + tid;
            int row = idx >> 3, c4 = idx & 7;
            int gr = mBase + row;
            pa[i] = (gr < M) ? *(const float4*)&A[(size_t)gr * K + kt + c4 * 4]
                             : make_float4(0.f, 0.f, 0.f, 0.f);
        }
        #pragma unroll
        for (int i = 0; i < 2; i++) {
            int idx = i * 256 + tid;
            int brow = idx >> 4, c8 = idx & 15;
            size_t g = (size_t)(kt + brow) * 256 + nCta + c8 * 8;
            pbh[i] = *(const uint4*)&Wh[g];
            pbl[i] = *(const uint4*)&Wl[g];
        }
    };

    auto store_s = [&](int buf) {
        __nv_bfloat16* base = sh + buf * STG;
        #pragma unroll
        for (int i = 0; i < 4; i++) {
            int idx = i * 256 + tid;
            int row = idx >> 3, c4 = idx & 7;
            const float* v = (const float*)&pa[i];
            uint32_t hh[2], ll[2];
            #pragma unroll
            for (int p = 0; p < 2; p++) {
                float x0 = v[2 * p], x1 = v[2 * p + 1];
                __nv_bfloat16 h0 = __float2bfloat16_rn(x0);
                __nv_bfloat16 h1 = __float2bfloat16_rn(x1);
                float l0 = x0 - __bfloat162float(h0);
                float l1 = x1 - __bfloat162float(h1);
                __nv_bfloat162 hw; hw.x = h0; hw.y = h1;
                __nv_bfloat162 lw; lw.x = __float2bfloat16_rn(l0);
                lw.y = __float2bfloat16_rn(l1);
                hh[p] = *(uint32_t*)&hw;
                ll[p] = *(uint32_t*)&lw;
            }
            *(uint2*)&base[AH + row * 40 + c4 * 4] = make_uint2(hh[0], hh[1]);
            *(uint2*)&base[AL + row * 40 + c4 * 4] = make_uint2(ll[0], ll[1]);
        }
        #pragma unroll
        for (int i = 0; i < 2; i++) {
            int idx = i * 256 + tid;
            int brow = idx >> 4, c8 = idx & 15;
            *(uint4*)&base[BH + brow * 136 + c8 * 8] = pbh[i];
            *(uint4*)&base[BL + brow * 136 + c8 * 8] = pbl[i];
        }
    };

    auto compute = [&](int buf) {
        const uint32_t base = shb + (uint32_t)buf * STG * 2;   // bytes
        #pragma unroll
        for (int k16 = 0; k16 < 2; k16++) {
            const int krow = k16 * 16;
            uint32_t ah[2][4], al[2][4], bh[8][2], bl[8][2];
            #pragma unroll
            for (int i = 0; i < 2; i++) {
                uint32_t ra = base + (uint32_t)(AH * 2) +
                    (uint32_t)(((wm * 32 + i * 16 + (lane & 15)) * 40 +
                                krow + ((lane >> 4) << 3)) * 2);
                ldsm_x4(ah[i], ra);
                ldsm_x4(al[i], ra + (uint32_t)((AL - AH) * 2));
            }
            #pragma unroll
            for (int j = 0; j < 4; j++) {
                uint32_t rb = base + (uint32_t)(BH * 2) +
                    (uint32_t)(((krow + (lane & 15)) * 136 +
                                wn * 64 + j * 16 + ((lane >> 4) << 3)) * 2);
                uint32_t t[4];
                ldsm_x4_t(t, rb);
                bh[2*j][0] = t[0]; bh[2*j][1] = t[1];
                bh[2*j+1][0] = t[2]; bh[2*j+1][1] = t[3];
                ldsm_x4_t(t, rb + (uint32_t)((BL - BH) * 2));
                bl[2*j][0] = t[0]; bl[2*j][1] = t[1];
                bl[2*j+1][0] = t[2]; bl[2*j+1][1] = t[3];
            }
            #pragma unroll
            for (int i = 0; i < 2; i++)
                #pragma unroll
                for (int j = 0; j < 8; j++) {
                    mma_bf16(acc[i][j], ah[i], bh[j]);
                    mma_bf16(acc[i][j], al[i], bh[j]);
                    mma_bf16(acc[i][j], ah[i], bl[j]);
                }
        }
    };

    load_g(0);
    store_s(0);
    __syncthreads();
    #pragma unroll
    for (int s = 0; s < NST; s++) {
        if (s + 1 < NST) load_g(s + 1);
        compute(s & 1);
        if (s + 1 < NST) {
            store_s((s + 1) & 1);
            __syncthreads();
        }
    }

    // epilogue: bias + relu, float2 stores
    const int trow = lane >> 2;
    const int tcol = (lane & 3) * 2;
    #pragma unroll
    for (int i = 0; i < 2; i++) {
        int r0 = mBase + wm * 32 + i * 16 + trow;
        #pragma unroll
        for (int j = 0; j < 8; j++) {
            int col = nCta + wn * 64 + j * 8 + tcol;
            float2 bv = *(const float2*)&bias[col];
            if (r0 < M) {
                float2 o;
                o.x = fmaxf(acc[i][j][0] + bv.x, 0.f);
                o.y = fmaxf(acc[i][j][1] + bv.y, 0.f);
                *(float2*)&C[(size_t)r0 * 256 + col] = o;
            }
            if (r0 + 8 < M) {
                float2 o;
                o.x = fmaxf(acc[i][j][2] + bv.x, 0.f);
                o.y = fmaxf(acc[i][j][3] + bv.y, 0.f);
                *(float2*)&C[(size_t)(r0 + 8) * 256 + col] = o;
            }
        }
    }
}

// ---------------- launch -----------------------------------------------------
extern "C" void kernel_launch(void* const* d_in, const int* in_sizes, int n_in,
                              void* d_out, int out_size) {
    const float* X    = (const float*)d_in[0];
    const float* eps  = (const float*)d_in[1];
    const int*   esrc = (const int*)d_in[2];
    const int*   edst = (const int*)d_in[3];
    const float* W0   = (const float*)d_in[4];
    const float* b0   = (const float*)d_in[5];
    const float* W1   = (const float*)d_in[6];
    const float* b1   = (const float*)d_in[7];
    const float* e0   = (const float*)d_in[8];
    const float* e1   = (const float*)d_in[9];
    float* out = (float*)d_out;

    float *z0, *h1, *z1;
    __nv_bfloat16 *w0h, *w0l, *w1h, *w1l;
    cudaGetSymbolAddress((void**)&z0, g_z0);
    cudaGetSymbolAddress((void**)&h1, g_h1);
    cudaGetSymbolAddress((void**)&z1, g_z1);
    cudaGetSymbolAddress((void**)&w0h, g_w0h);
    cudaGetSymbolAddress((void**)&w0l, g_w0l);
    cudaGetSymbolAddress((void**)&w1h, g_w1h);
    cudaGetSymbolAddress((void**)&w1l, g_w1l);

    const int DYN = 2 * 18944 * 2;   // 75776 bytes
    cudaFuncSetAttribute(gemm_mma<DH0>, cudaFuncAttributeMaxDynamicSharedMemorySize, DYN);
    cudaFuncSetAttribute(gemm_mma<DH1>, cudaFuncAttributeMaxDynamicSharedMemorySize, DYN);

    // 1) fused init (deg zero + weight split), eps bit-pack, CSR build
    init_kernel<<<(DH1 * 256 + 255) / 256, 256>>>(W0, W1);
    pack_eps_kernel<<<(MROWS * 2 * 32 + 255) / 256, 256>>>(eps);
    count_deg_kernel<<<(NEDGES + 255) / 256, 256>>>(edst);
    block_scan_kernel<<<NSCANB, 256>>>();
    scan_bsum_kernel<<<1, 256>>>();
    add_off_kernel<<<NSCANB, 256>>>();
    fill_kernel<<<(NEDGES + 255) / 256, 256>>>(esrc, edst);

    dim3 ggrid((MROWS + 127) / 128, 2);

    // 2) layer 0
    agg0_kernel<<<NNODES, DH0>>>(X, z0, e0);
    gemm_mma<DH0><<<ggrid, 256, DYN>>>(z0, w0h, w0l, b0, h1, MROWS);

    // 3) layer 1 (outer relu idempotent with layer relu)
    agg_kernel<DH1><<<NNODES, DH1>>>(h1, z1, e1);
    gemm_mma<DH1><<<ggrid, 256, DYN>>>(z1, w1h, w1l, b1, out, MROWS);

    // 4) second output (epsilon) if the harness buffer includes it
    if ((size_t)out_size >= OUT_MAIN + EPS_ELEMS) {
        cudaMemcpyAsync(out + OUT_MAIN, eps, EPS_ELEMS * sizeof(float),
                        cudaMemcpyDeviceToDevice);
    }
}